// round 2
// baseline (speedup 1.0000x reference)
#include <cuda_runtime.h>
#include <cuda_bf16.h>
#include <math.h>

// Problem constants (fixed by the reference)
#define B_ 64
#define S_ 512
#define H_ 1024
#define K3 3072            // 3*H

// GEMM tiling
#define BM 64
#define BN 64
#define BK 16
#define KS 12              // K-split factor
#define KCH (K3 / KS)      // 256 K per block
#define PAD 4
#define LDS_ (BM + PAD)    // 68, multiple of 4 -> float4-aligned smem rows

// Scratch (allocation-free rule: __device__ globals)
__device__ float g_feats[B_ * K3];            // 786 KB
__device__ float g_part[KS * B_ * H_];        // 3 MB partial GEMM results

// ---------------------------------------------------------------------------
// Kernel 1: build feats = [first_token | mean(subj range) | mean(obj range)]
// grid (B, 3), 256 threads, float4 vectorized (H=1024 -> 256 float4 per row)
// ---------------------------------------------------------------------------
__global__ __launch_bounds__(256) void feats_kernel(
    const float* __restrict__ hs,
    const int* __restrict__ subj,
    const int* __restrict__ obj)
{
    const int b   = blockIdx.x;
    const int seg = blockIdx.y;
    const int tid = threadIdx.x;   // one float4 (4 h-values) per thread

    const float4* base = (const float4*)(hs + (size_t)b * S_ * H_);
    float4* out = (float4*)(g_feats + (size_t)b * K3 + seg * H_);

    if (seg == 0) {
        out[tid] = base[tid];
    } else {
        const int* rng = (seg == 1 ? subj : obj) + b * 2;
        const int s0 = rng[0];
        const int s1 = rng[1];
        const int cnt = s1 - s0;
        const float inv = 1.0f / (float)(cnt > 0 ? cnt : 1);
        float4 acc = make_float4(0.f, 0.f, 0.f, 0.f);
        for (int s = s0; s < s1; ++s) {
            const float4 v = base[(size_t)s * (H_ / 4) + tid];
            acc.x += v.x; acc.y += v.y; acc.z += v.z; acc.w += v.w;
        }
        acc.x *= inv; acc.y *= inv; acc.z *= inv; acc.w *= inv;
        out[tid] = acc;
    }
}

// ---------------------------------------------------------------------------
// Kernel 2: K-split GEMM partials, double-buffered smem.
// out_partial[kb][m][n] = sum_{k in chunk kb} feats[m][k] * W[n][k]
// grid (N/BN = 16, KS = 12), 256 threads, 4x4 microtile per thread
// ---------------------------------------------------------------------------
__global__ __launch_bounds__(256) void gemm_partial_kernel(
    const float* __restrict__ Wm)
{
    __shared__ float As[2][BK][LDS_];   // A^T tile: [k][m]
    __shared__ float Bs[2][BK][LDS_];   // W^T tile: [k][n]

    const int nb  = blockIdx.x;
    const int kb  = blockIdx.y;
    const int tid = threadIdx.x;

    // loading layout: each thread loads one float4 along K
    const int lrow = tid >> 2;          // 0..63  (m or n row)
    const int lk   = (tid & 3) << 2;    // 0,4,8,12 (k offset within BK)

    // compute layout: 16x16 threads, 4x4 outputs each
    const int tn = (tid & 15) << 2;     // n offset in tile
    const int tm = (tid >> 4) << 2;     // m offset in tile

    const int n0 = nb * BN;
    const int k0 = kb * KCH;

    const float* aptr = g_feats + (size_t)lrow * K3 + k0 + lk;
    const float* wptr = Wm + (size_t)(n0 + lrow) * K3 + k0 + lk;

    float acc[4][4];
    #pragma unroll
    for (int i = 0; i < 4; ++i)
        #pragma unroll
        for (int j = 0; j < 4; ++j)
            acc[i][j] = 0.0f;

    // prologue: load tile 0 into buffer 0
    {
        const float4 av = *(const float4*)aptr;
        const float4 wv = *(const float4*)wptr;
        As[0][lk + 0][lrow] = av.x;
        As[0][lk + 1][lrow] = av.y;
        As[0][lk + 2][lrow] = av.z;
        As[0][lk + 3][lrow] = av.w;
        Bs[0][lk + 0][lrow] = wv.x;
        Bs[0][lk + 1][lrow] = wv.y;
        Bs[0][lk + 2][lrow] = wv.z;
        Bs[0][lk + 3][lrow] = wv.w;
    }
    __syncthreads();

    const int NT = KCH / BK;            // 16 tiles
    #pragma unroll 1
    for (int t = 0; t < NT; ++t) {
        const int cur = t & 1;
        const int nxt = cur ^ 1;

        // issue next tile's global loads early (hide behind FMAs)
        float4 av, wv;
        const bool have_next = (t + 1 < NT);
        if (have_next) {
            av = *(const float4*)(aptr + (t + 1) * BK);
            wv = *(const float4*)(wptr + (t + 1) * BK);
        }

        #pragma unroll
        for (int kk = 0; kk < BK; ++kk) {
            const float4 a = *(const float4*)&As[cur][kk][tm];
            const float4 w = *(const float4*)&Bs[cur][kk][tn];
            acc[0][0] += a.x * w.x; acc[0][1] += a.x * w.y;
            acc[0][2] += a.x * w.z; acc[0][3] += a.x * w.w;
            acc[1][0] += a.y * w.x; acc[1][1] += a.y * w.y;
            acc[1][2] += a.y * w.z; acc[1][3] += a.y * w.w;
            acc[2][0] += a.z * w.x; acc[2][1] += a.z * w.y;
            acc[2][2] += a.z * w.z; acc[2][3] += a.z * w.w;
            acc[3][0] += a.w * w.x; acc[3][1] += a.w * w.y;
            acc[3][2] += a.w * w.z; acc[3][3] += a.w * w.w;
        }

        if (have_next) {
            As[nxt][lk + 0][lrow] = av.x;
            As[nxt][lk + 1][lrow] = av.y;
            As[nxt][lk + 2][lrow] = av.z;
            As[nxt][lk + 3][lrow] = av.w;
            Bs[nxt][lk + 0][lrow] = wv.x;
            Bs[nxt][lk + 1][lrow] = wv.y;
            Bs[nxt][lk + 2][lrow] = wv.z;
            Bs[nxt][lk + 3][lrow] = wv.w;
            __syncthreads();
        }
    }

    // store 4x4 microtile as 4 float4s
    #pragma unroll
    for (int i = 0; i < 4; ++i) {
        float4 v;
        v.x = acc[i][0]; v.y = acc[i][1]; v.z = acc[i][2]; v.w = acc[i][3];
        *(float4*)(g_part + ((size_t)kb * B_ + (tm + i)) * H_ + n0 + tn) = v;
    }
}

// ---------------------------------------------------------------------------
// Kernel 3: reduce K-split partials + bias + tanh
// grid 256 blocks x 256 threads = 65536 = B*H
// ---------------------------------------------------------------------------
__global__ __launch_bounds__(256) void reduce_kernel(
    const float* __restrict__ bias,
    float* __restrict__ out)
{
    const int idx = blockIdx.x * 256 + threadIdx.x;
    const int b = idx >> 10;        // / H_
    const int n = idx & (H_ - 1);

    float s = bias[n];
    #pragma unroll
    for (int kb = 0; kb < KS; ++kb)
        s += g_part[((size_t)kb * B_ + b) * H_ + n];

    out[idx] = tanhf(s);
}

// ---------------------------------------------------------------------------
extern "C" void kernel_launch(void* const* d_in, const int* in_sizes, int n_in,
                              void* d_out, int out_size)
{
    const float* hs   = (const float*)d_in[0];   // (B, S, H) f32
    const int*   subj = (const int*)  d_in[1];   // (B, 2) i32
    const int*   obj  = (const int*)  d_in[2];   // (B, 2) i32
    const float* Wm   = (const float*)d_in[3];   // (H, 3H) f32
    const float* bias = (const float*)d_in[4];   // (H,) f32
    float*       out  = (float*)d_out;           // (B, H) f32

    (void)in_sizes; (void)n_in; (void)out_size;

    feats_kernel<<<dim3(B_, 3), 256>>>(hs, subj, obj);
    gemm_partial_kernel<<<dim3(H_ / BN, KS), 256>>>(Wm);
    reduce_kernel<<<(B_ * H_) / 256, 256>>>(bias, out);
}

// round 3
// speedup vs baseline: 1.0078x; 1.0078x over previous
#include <cuda_runtime.h>
#include <cuda_bf16.h>
#include <math.h>

// Problem constants (fixed by the reference)
#define B_ 64
#define S_ 512
#define H_ 1024
#define K3 3072            // 3*H

// GEMM tiling
#define BM 64
#define BN 64
#define BK 16
#define KS 16              // K-split factor -> grid 16x16 = 256 blocks
#define KCH (K3 / KS)      // 192 K per block
#define NT (KCH / BK)      // 12 tiles
#define PAD 4
#define LDS_ (BM + PAD)    // 68 floats per Bs row
#define LDS2_ (2 * BM + 2) // 130 floats per duplicated-As row (8B aligned rows)

// Scratch (allocation-free rule: __device__ globals)
__device__ float g_feats[B_ * K3];            // 786 KB
__device__ float g_part[KS * B_ * H_];        // 4 MB partial GEMM results

// packed fp32x2 helpers -------------------------------------------------------
__device__ __forceinline__ void ffma2(unsigned long long& d,
                                      unsigned long long a,
                                      unsigned long long b)
{
    asm("fma.rn.f32x2 %0, %1, %2, %0;" : "+l"(d) : "l"(a), "l"(b));
}

// ---------------------------------------------------------------------------
// Kernel 1: build feats = [first_token | mean(subj range) | mean(obj range)]
// grid (B, 3), 256 threads, float4 vectorized, 8-way MLP on the s-loop
// ---------------------------------------------------------------------------
__global__ __launch_bounds__(256) void feats_kernel(
    const float* __restrict__ hs,
    const int* __restrict__ subj,
    const int* __restrict__ obj)
{
    const int b   = blockIdx.x;
    const int seg = blockIdx.y;
    const int tid = threadIdx.x;   // one float4 (4 h-values) per thread

    const float4* base = (const float4*)(hs + (size_t)b * S_ * H_);
    float4* out = (float4*)(g_feats + (size_t)b * K3 + seg * H_);

    if (seg == 0) {
        out[tid] = base[tid];
        return;
    }

    const int* rng = (seg == 1 ? subj : obj) + b * 2;
    const int s0 = rng[0];
    const int s1 = rng[1];
    const int cnt = s1 - s0;
    const float inv = 1.0f / (float)(cnt > 0 ? cnt : 1);

    float4 a0 = make_float4(0.f,0.f,0.f,0.f), a1 = a0, a2 = a0, a3 = a0;
    float4 a4 = a0, a5 = a0, a6 = a0, a7 = a0;

    const int HC = H_ / 4;   // 256 float4 per row
    const float4* p = base + (size_t)s0 * HC + tid;
    int s = s0;

    for (; s + 8 <= s1; s += 8, p += 8 * HC) {
        const float4 v0 = p[0 * HC];
        const float4 v1 = p[1 * HC];
        const float4 v2 = p[2 * HC];
        const float4 v3 = p[3 * HC];
        const float4 v4 = p[4 * HC];
        const float4 v5 = p[5 * HC];
        const float4 v6 = p[6 * HC];
        const float4 v7 = p[7 * HC];
        a0.x += v0.x; a0.y += v0.y; a0.z += v0.z; a0.w += v0.w;
        a1.x += v1.x; a1.y += v1.y; a1.z += v1.z; a1.w += v1.w;
        a2.x += v2.x; a2.y += v2.y; a2.z += v2.z; a2.w += v2.w;
        a3.x += v3.x; a3.y += v3.y; a3.z += v3.z; a3.w += v3.w;
        a4.x += v4.x; a4.y += v4.y; a4.z += v4.z; a4.w += v4.w;
        a5.x += v5.x; a5.y += v5.y; a5.z += v5.z; a5.w += v5.w;
        a6.x += v6.x; a6.y += v6.y; a6.z += v6.z; a6.w += v6.w;
        a7.x += v7.x; a7.y += v7.y; a7.z += v7.z; a7.w += v7.w;
    }
    // remainder, 4-way
    for (; s + 4 <= s1; s += 4, p += 4 * HC) {
        const float4 v0 = p[0 * HC];
        const float4 v1 = p[1 * HC];
        const float4 v2 = p[2 * HC];
        const float4 v3 = p[3 * HC];
        a0.x += v0.x; a0.y += v0.y; a0.z += v0.z; a0.w += v0.w;
        a1.x += v1.x; a1.y += v1.y; a1.z += v1.z; a1.w += v1.w;
        a2.x += v2.x; a2.y += v2.y; a2.z += v2.z; a2.w += v2.w;
        a3.x += v3.x; a3.y += v3.y; a3.z += v3.z; a3.w += v3.w;
    }
    for (; s < s1; ++s, p += HC) {
        const float4 v0 = *p;
        a0.x += v0.x; a0.y += v0.y; a0.z += v0.z; a0.w += v0.w;
    }

    a0.x += a1.x + a2.x + a3.x + a4.x + a5.x + a6.x + a7.x;
    a0.y += a1.y + a2.y + a3.y + a4.y + a5.y + a6.y + a7.y;
    a0.z += a1.z + a2.z + a3.z + a4.z + a5.z + a6.z + a7.z;
    a0.w += a1.w + a2.w + a3.w + a4.w + a5.w + a6.w + a7.w;

    a0.x *= inv; a0.y *= inv; a0.z *= inv; a0.w *= inv;
    out[tid] = a0;
}

// ---------------------------------------------------------------------------
// Kernel 2: K-split GEMM partials, double-buffered smem, packed f32x2 FMA.
// out_partial[kb][m][n] = sum_{k in chunk kb} feats[m][k] * W[n][k]
// grid (16, 16), 256 threads, 4x4 microtile (as 4x2 packed pairs) per thread
// ---------------------------------------------------------------------------
__global__ __launch_bounds__(256) void gemm_partial_kernel(
    const float* __restrict__ Wm)
{
    __shared__ float As2[2][BK][LDS2_];  // A tile duplicated: [k][2m]={v,v}
    __shared__ float Bs[2][BK][LDS_];    // W^T tile: [k][n]

    const int nb  = blockIdx.x;
    const int kb  = blockIdx.y;
    const int tid = threadIdx.x;

    // loading layout: each thread loads one float4 along K
    const int lrow = tid >> 2;          // 0..63  (m or n row)
    const int lk   = (tid & 3) << 2;    // 0,4,8,12 (k offset within BK)

    // compute layout: 16x16 threads, 4x4 outputs each
    const int tn = (tid & 15) << 2;     // n offset in tile
    const int tm = (tid >> 4) << 2;     // m offset in tile

    const int n0 = nb * BN;
    const int k0 = kb * KCH;

    const float* aptr = g_feats + (size_t)lrow * K3 + k0 + lk;
    const float* wptr = Wm + (size_t)(n0 + lrow) * K3 + k0 + lk;

    unsigned long long acc[4][2];
    #pragma unroll
    for (int i = 0; i < 4; ++i) { acc[i][0] = 0ull; acc[i][1] = 0ull; }

    // prologue: load tile 0 into buffer 0
    {
        const float4 av = *(const float4*)aptr;
        const float4 wv = *(const float4*)wptr;
        *(float2*)&As2[0][lk + 0][2 * lrow] = make_float2(av.x, av.x);
        *(float2*)&As2[0][lk + 1][2 * lrow] = make_float2(av.y, av.y);
        *(float2*)&As2[0][lk + 2][2 * lrow] = make_float2(av.z, av.z);
        *(float2*)&As2[0][lk + 3][2 * lrow] = make_float2(av.w, av.w);
        Bs[0][lk + 0][lrow] = wv.x;
        Bs[0][lk + 1][lrow] = wv.y;
        Bs[0][lk + 2][lrow] = wv.z;
        Bs[0][lk + 3][lrow] = wv.w;
    }
    __syncthreads();

    #pragma unroll 1
    for (int t = 0; t < NT; ++t) {
        const int cur = t & 1;
        const int nxt = cur ^ 1;

        // issue next tile's global loads early (hide behind FMAs)
        float4 av, wv;
        const bool have_next = (t + 1 < NT);
        if (have_next) {
            av = *(const float4*)(aptr + (t + 1) * BK);
            wv = *(const float4*)(wptr + (t + 1) * BK);
        }

        #pragma unroll
        for (int kk = 0; kk < BK; ++kk) {
            const unsigned long long* wrow =
                (const unsigned long long*)&Bs[cur][kk][tn];
            const unsigned long long w01 = wrow[0];
            const unsigned long long w23 = wrow[1];
            const unsigned long long* arow =
                (const unsigned long long*)&As2[cur][kk][2 * tm];
            const unsigned long long b0 = arow[0];
            const unsigned long long b1 = arow[1];
            const unsigned long long b2 = arow[2];
            const unsigned long long b3 = arow[3];
            ffma2(acc[0][0], b0, w01); ffma2(acc[0][1], b0, w23);
            ffma2(acc[1][0], b1, w01); ffma2(acc[1][1], b1, w23);
            ffma2(acc[2][0], b2, w01); ffma2(acc[2][1], b2, w23);
            ffma2(acc[3][0], b3, w01); ffma2(acc[3][1], b3, w23);
        }

        if (have_next) {
            __syncthreads();   // everyone done reading buf nxt from 2 tiles ago
            *(float2*)&As2[nxt][lk + 0][2 * lrow] = make_float2(av.x, av.x);
            *(float2*)&As2[nxt][lk + 1][2 * lrow] = make_float2(av.y, av.y);
            *(float2*)&As2[nxt][lk + 2][2 * lrow] = make_float2(av.z, av.z);
            *(float2*)&As2[nxt][lk + 3][2 * lrow] = make_float2(av.w, av.w);
            Bs[nxt][lk + 0][lrow] = wv.x;
            Bs[nxt][lk + 1][lrow] = wv.y;
            Bs[nxt][lk + 2][lrow] = wv.z;
            Bs[nxt][lk + 3][lrow] = wv.w;
            __syncthreads();
        }
    }

    // store 4x4 microtile as 4 float4s
    #pragma unroll
    for (int i = 0; i < 4; ++i) {
        union { unsigned long long u; float2 f; } lo, hi;
        lo.u = acc[i][0];
        hi.u = acc[i][1];
        float4 v;
        v.x = lo.f.x; v.y = lo.f.y; v.z = hi.f.x; v.w = hi.f.y;
        *(float4*)(g_part + ((size_t)kb * B_ + (tm + i)) * H_ + n0 + tn) = v;
    }
}

// ---------------------------------------------------------------------------
// Kernel 3: reduce K-split partials + bias + tanh
// grid 256 blocks x 256 threads = 65536 = B*H
// ---------------------------------------------------------------------------
__global__ __launch_bounds__(256) void reduce_kernel(
    const float* __restrict__ bias,
    float* __restrict__ out)
{
    const int idx = blockIdx.x * 256 + threadIdx.x;
    const int b = idx >> 10;        // / H_
    const int n = idx & (H_ - 1);

    float s = bias[n];
    #pragma unroll
    for (int kb = 0; kb < KS; ++kb)
        s += g_part[((size_t)kb * B_ + b) * H_ + n];

    out[idx] = tanhf(s);
}

// ---------------------------------------------------------------------------
extern "C" void kernel_launch(void* const* d_in, const int* in_sizes, int n_in,
                              void* d_out, int out_size)
{
    const float* hs   = (const float*)d_in[0];   // (B, S, H) f32
    const int*   subj = (const int*)  d_in[1];   // (B, 2) i32
    const int*   obj  = (const int*)  d_in[2];   // (B, 2) i32
    const float* Wm   = (const float*)d_in[3];   // (H, 3H) f32
    const float* bias = (const float*)d_in[4];   // (H,) f32
    float*       out  = (float*)d_out;           // (B, H) f32

    (void)in_sizes; (void)n_in; (void)out_size;

    feats_kernel<<<dim3(B_, 3), 256>>>(hs, subj, obj);
    gemm_partial_kernel<<<dim3(H_ / BN, KS), 256>>>(Wm);
    reduce_kernel<<<(B_ * H_) / 256, 256>>>(bias, out);
}

// round 5
// speedup vs baseline: 1.5315x; 1.5196x over previous
#include <cuda_runtime.h>
#include <cuda_bf16.h>
#include <math.h>
#include <stdint.h>

// Problem constants
#define B_ 64
#define S_ 512
#define H_ 1024
#define K3 3072            // 3*H

// GEMM config
#define BN_ 128            // n-tile per CTA
#define KS 16              // K-split -> grid (8, 16) = 128 CTAs
#define KC (K3 / KS)       // 192 K per CTA
#define NSTG (KC / 16)     // 12 k16 stages
#define ASTR 24            // smem A row stride in bf16 (48 B, conflict-free for ldmatrix)
#define WSTR 24            // smem W row stride in bf16

// Scratch (__device__ globals; no allocation allowed)
__device__ __align__(16) __nv_bfloat16 g_Ah[B_ * K3];   // feats hi
__device__ __align__(16) __nv_bfloat16 g_Al[B_ * K3];   // feats lo
__device__ __align__(16) float g_part[KS * B_ * H_];    // 4 MB partials

// ---------------------------------------------------------------------------
// helpers
// ---------------------------------------------------------------------------
__device__ __forceinline__ uint32_t smem_u32(const void* p) {
    return (uint32_t)__cvta_generic_to_shared(p);
}
__device__ __forceinline__ void ldmatrix_x4(uint32_t* r, uint32_t addr) {
    asm volatile("ldmatrix.sync.aligned.m8n8.x4.shared.b16 {%0,%1,%2,%3}, [%4];"
                 : "=r"(r[0]), "=r"(r[1]), "=r"(r[2]), "=r"(r[3]) : "r"(addr));
}
__device__ __forceinline__ void mma_bf16(float* c, const uint32_t* a,
                                         uint32_t b0, uint32_t b1) {
    asm volatile(
        "mma.sync.aligned.m16n8k16.row.col.f32.bf16.bf16.f32 "
        "{%0,%1,%2,%3}, {%4,%5,%6,%7}, {%8,%9}, {%0,%1,%2,%3};"
        : "+f"(c[0]), "+f"(c[1]), "+f"(c[2]), "+f"(c[3])
        : "r"(a[0]), "r"(a[1]), "r"(a[2]), "r"(a[3]), "r"(b0), "r"(b1));
}
__device__ __forceinline__ void split_bf16(float x, __nv_bfloat16& h, __nv_bfloat16& l) {
    h = __float2bfloat16_rn(x);
    l = __float2bfloat16_rn(x - __bfloat162float(h));
}

// ---------------------------------------------------------------------------
// Kernel 1: feats -> bf16 hi/lo.  grid (B, 3), 1024 threads.
// seg 0: copy first token.  seg 1/2: range mean, 4 s-slices x 256 h4-slots.
// ---------------------------------------------------------------------------
__global__ __launch_bounds__(1024) void feats_kernel(
    const float* __restrict__ hs,
    const int* __restrict__ subj,
    const int* __restrict__ obj)
{
    __shared__ float4 red[3][256];

    const int b   = blockIdx.x;
    const int seg = blockIdx.y;
    const int tid = threadIdx.x;
    const int HC  = H_ / 4;                 // 256 float4 per row

    const float4* base = (const float4*)(hs + (size_t)b * S_ * H_);

    float4 acc = make_float4(0.f, 0.f, 0.f, 0.f);
    const int h4 = tid & 255;
    float inv = 1.0f;

    if (seg == 0) {
        if (tid >= 256) return;
        acc = base[h4];
    } else {
        const int slice = tid >> 8;         // 0..3
        const int* rng = (seg == 1 ? subj : obj) + b * 2;
        const int s0 = rng[0];
        const int s1 = rng[1];
        const int cnt = s1 - s0;
        inv = 1.0f / (float)(cnt > 0 ? cnt : 1);

        float4 a0 = make_float4(0.f,0.f,0.f,0.f), a1 = a0;
        int s = s0 + slice;
        for (; s + 4 < s1; s += 8) {
            const float4 v0 = base[(size_t)s * HC + h4];
            const float4 v1 = base[(size_t)(s + 4) * HC + h4];
            a0.x += v0.x; a0.y += v0.y; a0.z += v0.z; a0.w += v0.w;
            a1.x += v1.x; a1.y += v1.y; a1.z += v1.z; a1.w += v1.w;
        }
        if (s < s1) {
            const float4 v0 = base[(size_t)s * HC + h4];
            a0.x += v0.x; a0.y += v0.y; a0.z += v0.z; a0.w += v0.w;
        }
        acc.x = a0.x + a1.x; acc.y = a0.y + a1.y;
        acc.z = a0.z + a1.z; acc.w = a0.w + a1.w;

        if (slice > 0) red[slice - 1][h4] = acc;
        __syncthreads();
        if (slice != 0) return;
        const float4 r0 = red[0][h4];
        const float4 r1 = red[1][h4];
        const float4 r2 = red[2][h4];
        acc.x += r0.x + r1.x + r2.x;
        acc.y += r0.y + r1.y + r2.y;
        acc.z += r0.z + r1.z + r2.z;
        acc.w += r0.w + r1.w + r2.w;
        acc.x *= inv; acc.y *= inv; acc.z *= inv; acc.w *= inv;
    }

    // split to bf16 hi/lo and store 4 elems (8 B each array)
    __nv_bfloat16 h[4], l[4];
    split_bf16(acc.x, h[0], l[0]);
    split_bf16(acc.y, h[1], l[1]);
    split_bf16(acc.z, h[2], l[2]);
    split_bf16(acc.w, h[3], l[3]);

    const size_t off = (size_t)b * K3 + seg * H_ + h4 * 4;
    *(__nv_bfloat162*)(g_Ah + off)     = __halves2bfloat162(h[0], h[1]);
    *(__nv_bfloat162*)(g_Ah + off + 2) = __halves2bfloat162(h[2], h[3]);
    *(__nv_bfloat162*)(g_Al + off)     = __halves2bfloat162(l[0], l[1]);
    *(__nv_bfloat162*)(g_Al + off + 2) = __halves2bfloat162(l[2], l[3]);
}

// ---------------------------------------------------------------------------
// Kernel 2: split-bf16 3-term tensor-core GEMM partials.
// grid (H/BN_ = 8, KS = 16), 256 threads = 8 warps (2 m-warps x 4 n-warps).
// CTA tile: 64(m) x 128(n) x KC(k).  W converted f32->bf16 hi/lo in-kernel.
// W stored [n][k] (k contiguous) == .col layout for B: NON-trans ldmatrix.
// ---------------------------------------------------------------------------
__global__ __launch_bounds__(256) void gemm_partial_kernel(
    const float* __restrict__ Wm)
{
    __shared__ __nv_bfloat16 sAh[2][B_ * ASTR];     // 3 KB x 2
    __shared__ __nv_bfloat16 sAl[2][B_ * ASTR];
    __shared__ __nv_bfloat16 sWh[2][BN_ * WSTR];    // 6 KB x 2
    __shared__ __nv_bfloat16 sWl[2][BN_ * WSTR];

    const int nb   = blockIdx.x;
    const int kb   = blockIdx.y;
    const int tid  = threadIdx.x;
    const int wid  = tid >> 5;
    const int lane = tid & 31;

    const int n0 = nb * BN_;
    const int k0 = kb * KC;

    // ---- stage loads ----
    // A: threads 0-127 load Ah, 128-255 load Al. One uint4 = 8 bf16.
    const int ar = (tid & 127) >> 1;        // row 0..63
    const int ap = tid & 1;                 // 0/1 -> k-halves of 16
    const __nv_bfloat16* gA = (tid < 128 ? g_Ah : g_Al);
    const __nv_bfloat16* aQ = gA + (size_t)ar * K3 + k0 + ap * 8;

    // W: 2 iters, each thread one float4 (4 k)
    const int wrow = tid >> 2;              // 0..63 (+64 on iter 1)
    const int wk4  = tid & 3;
    const float* wQ = Wm + (size_t)(n0 + wrow) * K3 + k0 + wk4 * 4;

    uint4  aReg;
    float4 wReg0, wReg1;

    auto load_stage = [&](int st) {
        aReg  = *(const uint4*)(aQ + st * 16);
        wReg0 = *(const float4*)(wQ + st * 16);
        wReg1 = *(const float4*)(wQ + (size_t)64 * K3 + st * 16);
    };
    auto store_stage = [&](int buf) {
        // A
        {
            __nv_bfloat16* dst = (tid < 128 ? sAh[buf] : sAl[buf]) + ar * ASTR + ap * 8;
            *(uint4*)dst = aReg;
        }
        // W: convert f32 -> hi/lo bf16
        #pragma unroll
        for (int r = 0; r < 2; ++r) {
            const float4 v = (r == 0) ? wReg0 : wReg1;
            __nv_bfloat16 h0,h1,h2,h3,l0,l1,l2,l3;
            split_bf16(v.x, h0, l0); split_bf16(v.y, h1, l1);
            split_bf16(v.z, h2, l2); split_bf16(v.w, h3, l3);
            const int row = wrow + r * 64;
            __nv_bfloat16* dh = sWh[buf] + row * WSTR + wk4 * 4;
            __nv_bfloat16* dl = sWl[buf] + row * WSTR + wk4 * 4;
            *(__nv_bfloat162*)(dh)     = __halves2bfloat162(h0, h1);
            *(__nv_bfloat162*)(dh + 2) = __halves2bfloat162(h2, h3);
            *(__nv_bfloat162*)(dl)     = __halves2bfloat162(l0, l1);
            *(__nv_bfloat162*)(dl + 2) = __halves2bfloat162(l2, l3);
        }
    };

    // ---- warp compute layout ----
    const int mw = wid & 1;                 // 0..1 -> m32
    const int nw = wid >> 1;                // 0..3 -> n32

    // ldmatrix lane address components (both operands non-trans)
    const int a_row = (lane & 15);          // + m base
    const int a_col = (lane >> 4) << 3;     // 0 / 8
    const int b_row = (lane & 7) | ((lane >> 4) << 3);   // n within 16-group
    const int b_col = ((lane >> 3) & 1) << 3;            // k half

    float acc[2][4][4];
    #pragma unroll
    for (int i = 0; i < 2; ++i)
        #pragma unroll
        for (int j = 0; j < 4; ++j)
            #pragma unroll
            for (int c = 0; c < 4; ++c) acc[i][j][c] = 0.f;

    load_stage(0);
    store_stage(0);
    __syncthreads();

    #pragma unroll 1
    for (int st = 0; st < NSTG; ++st) {
        const int cur = st & 1;
        const bool more = (st + 1 < NSTG);
        if (more) load_stage(st + 1);

        uint32_t ah[2][4], al[2][4], wh[2][4], wl[2][4];
        #pragma unroll
        for (int mi = 0; mi < 2; ++mi) {
            const int row = mw * 32 + mi * 16 + a_row;
            ldmatrix_x4(ah[mi], smem_u32(sAh[cur] + row * ASTR + a_col));
            ldmatrix_x4(al[mi], smem_u32(sAl[cur] + row * ASTR + a_col));
        }
        #pragma unroll
        for (int g = 0; g < 2; ++g) {
            const int row = nw * 32 + g * 16 + b_row;
            ldmatrix_x4(wh[g], smem_u32(sWh[cur] + row * WSTR + b_col));
            ldmatrix_x4(wl[g], smem_u32(sWl[cur] + row * WSTR + b_col));
        }

        #pragma unroll
        for (int mi = 0; mi < 2; ++mi)
            #pragma unroll
            for (int j = 0; j < 4; ++j) {
                const int g = j >> 1, hf = (j & 1) * 2;
                mma_bf16(acc[mi][j], ah[mi], wh[g][hf], wh[g][hf + 1]); // ah*wh
                mma_bf16(acc[mi][j], ah[mi], wl[g][hf], wl[g][hf + 1]); // ah*wl
                mma_bf16(acc[mi][j], al[mi], wh[g][hf], wh[g][hf + 1]); // al*wh
            }

        if (more) {
            __syncthreads();
            store_stage(cur ^ 1);
            __syncthreads();
        }
    }

    // ---- epilogue: write f32 partials ----
    const int c_row = lane >> 2;
    const int c_col = (lane & 3) * 2;
    float* pbase = g_part + (size_t)kb * (B_ * H_);
    #pragma unroll
    for (int mi = 0; mi < 2; ++mi) {
        #pragma unroll
        for (int j = 0; j < 4; ++j) {
            const int m = mw * 32 + mi * 16 + c_row;
            const int n = n0 + nw * 32 + j * 8 + c_col;
            *(float2*)(pbase + (size_t)m * H_ + n) =
                make_float2(acc[mi][j][0], acc[mi][j][1]);
            *(float2*)(pbase + (size_t)(m + 8) * H_ + n) =
                make_float2(acc[mi][j][2], acc[mi][j][3]);
        }
    }
}

// ---------------------------------------------------------------------------
// Kernel 3: reduce K-split partials + bias + tanh
// ---------------------------------------------------------------------------
__global__ __launch_bounds__(256) void reduce_kernel(
    const float* __restrict__ bias,
    float* __restrict__ out)
{
    const int idx = blockIdx.x * 256 + threadIdx.x;
    const int n = idx & (H_ - 1);

    float s = bias[n];
    #pragma unroll
    for (int kb = 0; kb < KS; ++kb)
        s += g_part[(size_t)kb * (B_ * H_) + idx];

    out[idx] = tanhf(s);
}

// ---------------------------------------------------------------------------
extern "C" void kernel_launch(void* const* d_in, const int* in_sizes, int n_in,
                              void* d_out, int out_size)
{
    const float* hs   = (const float*)d_in[0];   // (B, S, H) f32
    const int*   subj = (const int*)  d_in[1];   // (B, 2) i32
    const int*   obj  = (const int*)  d_in[2];   // (B, 2) i32
    const float* Wm   = (const float*)d_in[3];   // (H, 3H) f32
    const float* bias = (const float*)d_in[4];   // (H,) f32
    float*       out  = (float*)d_out;           // (B, H) f32

    (void)in_sizes; (void)n_in; (void)out_size;

    feats_kernel<<<dim3(B_, 3), 1024>>>(hs, subj, obj);
    gemm_partial_kernel<<<dim3(H_ / BN_, KS), 256>>>(Wm);
    reduce_kernel<<<(B_ * H_) / 256, 256>>>(bias, out);
}

// round 6
// speedup vs baseline: 1.5368x; 1.0034x over previous
#include <cuda_runtime.h>
#include <cuda_bf16.h>
#include <math.h>
#include <stdint.h>

// Problem constants
#define B_ 64
#define S_ 512
#define H_ 1024
#define K3 3072            // 3*H

// GEMM config
#define BN_ 64             // n-tile per CTA
#define KS 16              // K-split -> grid (16, 16) = 256 CTAs
#define KC (K3 / KS)       // 192 K per CTA
#define NSTG (KC / 16)     // 12 k16 stages
#define ASTR 24            // smem A row stride in bf16 (48 B)
#define WSTR 24            // smem W row stride in bf16

// Scratch (__device__ globals; no allocation allowed)
__device__ __align__(16) __nv_bfloat16 g_Ah[B_ * K3];   // feats hi
__device__ __align__(16) __nv_bfloat16 g_Al[B_ * K3];   // feats lo
__device__ __align__(16) float g_part[KS * B_ * H_];    // 4 MB partials

// ---------------------------------------------------------------------------
// helpers
// ---------------------------------------------------------------------------
__device__ __forceinline__ uint32_t smem_u32(const void* p) {
    return (uint32_t)__cvta_generic_to_shared(p);
}
__device__ __forceinline__ void ldmatrix_x4(uint32_t* r, uint32_t addr) {
    asm volatile("ldmatrix.sync.aligned.m8n8.x4.shared.b16 {%0,%1,%2,%3}, [%4];"
                 : "=r"(r[0]), "=r"(r[1]), "=r"(r[2]), "=r"(r[3]) : "r"(addr));
}
__device__ __forceinline__ void mma_bf16(float* c, const uint32_t* a,
                                         uint32_t b0, uint32_t b1) {
    asm volatile(
        "mma.sync.aligned.m16n8k16.row.col.f32.bf16.bf16.f32 "
        "{%0,%1,%2,%3}, {%4,%5,%6,%7}, {%8,%9}, {%0,%1,%2,%3};"
        : "+f"(c[0]), "+f"(c[1]), "+f"(c[2]), "+f"(c[3])
        : "r"(a[0]), "r"(a[1]), "r"(a[2]), "r"(a[3]), "r"(b0), "r"(b1));
}
__device__ __forceinline__ void split_bf16(float x, __nv_bfloat16& h, __nv_bfloat16& l) {
    h = __float2bfloat16_rn(x);
    l = __float2bfloat16_rn(x - __bfloat162float(h));
}

// ---------------------------------------------------------------------------
// Kernel 1: feats -> bf16 hi/lo.  grid (B, 3), 1024 threads.
// seg 0: copy first token.  seg 1/2: range mean.
// Range length <= 32 (reference guarantees), so 4 slices x 8 unrolled
// predicated loads covers any range; all loads issue in one batch (MLP 8).
// ---------------------------------------------------------------------------
__global__ __launch_bounds__(1024) void feats_kernel(
    const float* __restrict__ hs,
    const int* __restrict__ subj,
    const int* __restrict__ obj)
{
    __shared__ float4 red[3][256];

    const int b   = blockIdx.x;
    const int seg = blockIdx.y;
    const int tid = threadIdx.x;
    const int HC  = H_ / 4;                 // 256 float4 per row

    const float4* base = (const float4*)(hs + (size_t)b * S_ * H_);

    float4 acc = make_float4(0.f, 0.f, 0.f, 0.f);
    const int h4 = tid & 255;
    float inv = 1.0f;

    if (seg == 0) {
        if (tid >= 256) return;
        acc = base[h4];
    } else {
        const int slice = tid >> 8;         // 0..3
        const int* rng = (seg == 1 ? subj : obj) + b * 2;
        const int s0 = rng[0];
        const int s1 = rng[1];
        const int cnt = s1 - s0;
        inv = 1.0f / (float)(cnt > 0 ? cnt : 1);

        const int sb = s0 + slice;
        #pragma unroll
        for (int i = 0; i < 8; ++i) {       // covers lengths up to 32
            const int s = sb + i * 4;
            if (s < s1) {
                const float4 v = base[(size_t)s * HC + h4];
                acc.x += v.x; acc.y += v.y; acc.z += v.z; acc.w += v.w;
            }
        }

        if (slice > 0) red[slice - 1][h4] = acc;
        __syncthreads();
        if (slice != 0) return;
        const float4 r0 = red[0][h4];
        const float4 r1 = red[1][h4];
        const float4 r2 = red[2][h4];
        acc.x += r0.x + r1.x + r2.x;
        acc.y += r0.y + r1.y + r2.y;
        acc.z += r0.z + r1.z + r2.z;
        acc.w += r0.w + r1.w + r2.w;
        acc.x *= inv; acc.y *= inv; acc.z *= inv; acc.w *= inv;
    }

    // split to bf16 hi/lo and store
    __nv_bfloat16 h[4], l[4];
    split_bf16(acc.x, h[0], l[0]);
    split_bf16(acc.y, h[1], l[1]);
    split_bf16(acc.z, h[2], l[2]);
    split_bf16(acc.w, h[3], l[3]);

    const size_t off = (size_t)b * K3 + seg * H_ + h4 * 4;
    *(__nv_bfloat162*)(g_Ah + off)     = __halves2bfloat162(h[0], h[1]);
    *(__nv_bfloat162*)(g_Ah + off + 2) = __halves2bfloat162(h[2], h[3]);
    *(__nv_bfloat162*)(g_Al + off)     = __halves2bfloat162(l[0], l[1]);
    *(__nv_bfloat162*)(g_Al + off + 2) = __halves2bfloat162(l[2], l[3]);
}

// ---------------------------------------------------------------------------
// Kernel 2: split-bf16 3-term tensor-core GEMM partials.
// grid (H/BN_ = 16, KS = 16) = 256 CTAs, 256 threads = 8 warps (2m x 4n).
// CTA tile: 64(m) x 64(n) x 192(k).  3-deep register prefetch, fully
// unrolled 12-stage mainloop.  W [n][k] k-contiguous -> non-trans ldmatrix.
// ---------------------------------------------------------------------------
struct Stage { uint4 a; float4 w; };

__global__ __launch_bounds__(256) void gemm_partial_kernel(
    const float* __restrict__ Wm)
{
    __shared__ __nv_bfloat16 sAh[2][B_ * ASTR];     // 3 KB x 2
    __shared__ __nv_bfloat16 sAl[2][B_ * ASTR];
    __shared__ __nv_bfloat16 sWh[2][BN_ * WSTR];    // 3 KB x 2
    __shared__ __nv_bfloat16 sWl[2][BN_ * WSTR];

    const int nb   = blockIdx.x;
    const int kb   = blockIdx.y;
    const int tid  = threadIdx.x;
    const int wid  = tid >> 5;
    const int lane = tid & 31;

    const int n0 = nb * BN_;
    const int k0 = kb * KC;

    // A: threads 0-127 load Ah, 128-255 load Al. One uint4 = 8 bf16.
    const int ar = (tid & 127) >> 1;        // row 0..63
    const int ap = tid & 1;                 // k-half of 16
    const __nv_bfloat16* aQ =
        (tid < 128 ? g_Ah : g_Al) + (size_t)ar * K3 + k0 + ap * 8;

    // W: one float4 (4 k) per thread per stage
    const int wrow = tid >> 2;              // 0..63
    const int wk4  = tid & 3;
    const float* wQ = Wm + (size_t)(n0 + wrow) * K3 + k0 + wk4 * 4;

    auto ld_st = [&](int st) {
        Stage q;
        q.a = *(const uint4*)(aQ + st * 16);
        q.w = *(const float4*)(wQ + st * 16);
        return q;
    };
    auto store_stage = [&](int buf, const Stage& q) {
        *(uint4*)((tid < 128 ? sAh[buf] : sAl[buf]) + ar * ASTR + ap * 8) = q.a;
        __nv_bfloat16 h0,h1,h2,h3,l0,l1,l2,l3;
        split_bf16(q.w.x, h0, l0); split_bf16(q.w.y, h1, l1);
        split_bf16(q.w.z, h2, l2); split_bf16(q.w.w, h3, l3);
        __nv_bfloat16* dh = sWh[buf] + wrow * WSTR + wk4 * 4;
        __nv_bfloat16* dl = sWl[buf] + wrow * WSTR + wk4 * 4;
        *(__nv_bfloat162*)(dh)     = __halves2bfloat162(h0, h1);
        *(__nv_bfloat162*)(dh + 2) = __halves2bfloat162(h2, h3);
        *(__nv_bfloat162*)(dl)     = __halves2bfloat162(l0, l1);
        *(__nv_bfloat162*)(dl + 2) = __halves2bfloat162(l2, l3);
    };

    // warp compute layout: 2 m-warps x 4 n-warps; warp tile 32(m) x 16(n)
    const int mw = wid & 1;
    const int nw = wid >> 1;

    const int a_row = (lane & 15);
    const int a_col = (lane >> 4) << 3;
    const int b_row = (lane & 7) | ((lane >> 4) << 3);
    const int b_col = ((lane >> 3) & 1) << 3;

    float acc[2][2][4];
    #pragma unroll
    for (int i = 0; i < 2; ++i)
        #pragma unroll
        for (int j = 0; j < 2; ++j)
            #pragma unroll
            for (int c = 0; c < 4; ++c) acc[i][j][c] = 0.f;

    // prologue: stage 0 to smem; stages 1..3 into register ring (3 in flight)
    Stage q[3];
    q[0] = ld_st(0);
    store_stage(0, q[0]);
    q[1] = ld_st(1);
    q[2] = ld_st(2);
    q[0] = ld_st(3);          // slot(s) = s % 3
    __syncthreads();

    #pragma unroll
    for (int t = 0; t < NSTG; ++t) {
        const int cur = t & 1;

        uint32_t ah[2][4], al[2][4], wh[4], wl[4];
        #pragma unroll
        for (int mi = 0; mi < 2; ++mi) {
            const int row = mw * 32 + mi * 16 + a_row;
            ldmatrix_x4(ah[mi], smem_u32(sAh[cur] + row * ASTR + a_col));
            ldmatrix_x4(al[mi], smem_u32(sAl[cur] + row * ASTR + a_col));
        }
        {
            const int row = nw * 16 + b_row;
            ldmatrix_x4(wh, smem_u32(sWh[cur] + row * WSTR + b_col));
            ldmatrix_x4(wl, smem_u32(sWl[cur] + row * WSTR + b_col));
        }

        #pragma unroll
        for (int mi = 0; mi < 2; ++mi)
            #pragma unroll
            for (int j = 0; j < 2; ++j) {
                const int hf = j * 2;
                mma_bf16(acc[mi][j], ah[mi], wh[hf], wh[hf + 1]); // ah*wh
                mma_bf16(acc[mi][j], ah[mi], wl[hf], wl[hf + 1]); // ah*wl
                mma_bf16(acc[mi][j], al[mi], wh[hf], wh[hf + 1]); // al*wh
            }

        if (t + 1 < NSTG) {
            __syncthreads();                  // all done reading buf nxt (stage t-1)
            store_stage(cur ^ 1, q[(t + 1) % 3]);
            if (t + 4 < NSTG) q[(t + 1) % 3] = ld_st(t + 4);
            __syncthreads();
        }
    }

    // epilogue: f32 partials
    const int c_row = lane >> 2;
    const int c_col = (lane & 3) * 2;
    float* pbase = g_part + (size_t)kb * (B_ * H_);
    #pragma unroll
    for (int mi = 0; mi < 2; ++mi) {
        #pragma unroll
        for (int j = 0; j < 2; ++j) {
            const int m = mw * 32 + mi * 16 + c_row;
            const int n = n0 + nw * 16 + j * 8 + c_col;
            *(float2*)(pbase + (size_t)m * H_ + n) =
                make_float2(acc[mi][j][0], acc[mi][j][1]);
            *(float2*)(pbase + (size_t)(m + 8) * H_ + n) =
                make_float2(acc[mi][j][2], acc[mi][j][3]);
        }
    }
}

// ---------------------------------------------------------------------------
// Kernel 3: reduce K-split partials + bias + tanh (float4 vectorized)
// grid 64 x 256 threads; each thread one float4 (4 outputs), 16 MLP loads
// ---------------------------------------------------------------------------
__global__ __launch_bounds__(256) void reduce_kernel(
    const float* __restrict__ bias,
    float* __restrict__ out)
{
    const int idx4 = blockIdx.x * 256 + threadIdx.x;  // 0 .. B_*H_/4-1
    const int n4 = idx4 & (H_ / 4 - 1);

    const float4 bv = *(const float4*)(bias + n4 * 4);
    float4 s = bv;
    #pragma unroll
    for (int kb = 0; kb < KS; ++kb) {
        const float4 p = *(const float4*)(g_part + (size_t)kb * (B_ * H_) + idx4 * 4);
        s.x += p.x; s.y += p.y; s.z += p.z; s.w += p.w;
    }

    float4 o;
    o.x = tanhf(s.x); o.y = tanhf(s.y); o.z = tanhf(s.z); o.w = tanhf(s.w);
    *(float4*)(out + idx4 * 4) = o;
}

// ---------------------------------------------------------------------------
extern "C" void kernel_launch(void* const* d_in, const int* in_sizes, int n_in,
                              void* d_out, int out_size)
{
    const float* hs   = (const float*)d_in[0];   // (B, S, H) f32
    const int*   subj = (const int*)  d_in[1];   // (B, 2) i32
    const int*   obj  = (const int*)  d_in[2];   // (B, 2) i32
    const float* Wm   = (const float*)d_in[3];   // (H, 3H) f32
    const float* bias = (const float*)d_in[4];   // (H,) f32
    float*       out  = (float*)d_out;           // (B, H) f32

    (void)in_sizes; (void)n_in; (void)out_size;

    feats_kernel<<<dim3(B_, 3), 1024>>>(hs, subj, obj);
    gemm_partial_kernel<<<dim3(H_ / BN_, KS), 256>>>(Wm);
    reduce_kernel<<<(B_ * H_) / 1024, 256>>>(bias, out);
}

// round 7
// speedup vs baseline: 1.5581x; 1.0139x over previous
#include <cuda_runtime.h>
#include <cuda_bf16.h>
#include <math.h>
#include <stdint.h>

// Problem constants
#define B_ 64
#define S_ 512
#define H_ 1024
#define K3 3072            // 3*H

// GEMM config
#define BN_ 64             // n-tile per CTA
#define KS 16              // K-split -> grid (16, 16) = 256 CTAs
#define KC (K3 / KS)       // 192 K per CTA
#define NSTG (KC / 16)     // 12 k16 stages
#define ASTR 24            // smem A row stride in bf16 (48 B)
#define WSTR 24            // smem W row stride in bf16

// Scratch (__device__ globals; no allocation allowed)
__device__ __align__(16) __nv_bfloat16 g_Ah[B_ * K3];   // feats hi
__device__ __align__(16) __nv_bfloat16 g_Al[B_ * K3];   // feats lo
__device__ __align__(16) float g_part[KS * B_ * H_];    // 4 MB partials

// ---------------------------------------------------------------------------
// helpers
// ---------------------------------------------------------------------------
__device__ __forceinline__ uint32_t smem_u32(const void* p) {
    return (uint32_t)__cvta_generic_to_shared(p);
}
__device__ __forceinline__ void ldmatrix_x4(uint32_t* r, uint32_t addr) {
    asm volatile("ldmatrix.sync.aligned.m8n8.x4.shared.b16 {%0,%1,%2,%3}, [%4];"
                 : "=r"(r[0]), "=r"(r[1]), "=r"(r[2]), "=r"(r[3]) : "r"(addr));
}
__device__ __forceinline__ void mma_bf16(float* c, const uint32_t* a,
                                         uint32_t b0, uint32_t b1) {
    asm volatile(
        "mma.sync.aligned.m16n8k16.row.col.f32.bf16.bf16.f32 "
        "{%0,%1,%2,%3}, {%4,%5,%6,%7}, {%8,%9}, {%0,%1,%2,%3};"
        : "+f"(c[0]), "+f"(c[1]), "+f"(c[2]), "+f"(c[3])
        : "r"(a[0]), "r"(a[1]), "r"(a[2]), "r"(a[3]), "r"(b0), "r"(b1));
}
__device__ __forceinline__ void split_bf16(float x, __nv_bfloat16& h, __nv_bfloat16& l) {
    h = __float2bfloat16_rn(x);
    l = __float2bfloat16_rn(x - __bfloat162float(h));
}

// ---------------------------------------------------------------------------
// Kernel 1: feats -> bf16 hi/lo.
// grid (B, 3, 4): z splits the h-dimension 4-ways so per-block bytes <= 32KB
// and DRAM load spreads evenly across SMs (768 blocks).
// 256 threads = 4 s-slices x 64 h4-slots.  Range length <= 32.
// ---------------------------------------------------------------------------
__global__ __launch_bounds__(256) void feats_kernel(
    const float* __restrict__ hs,
    const int* __restrict__ subj,
    const int* __restrict__ obj)
{
    __shared__ float4 red[3][64];

    const int b   = blockIdx.x;
    const int seg = blockIdx.y;
    const int hz  = blockIdx.z;
    const int tid = threadIdx.x;
    const int HC  = H_ / 4;                  // 256 float4 per row

    const int h4    = hz * 64 + (tid & 63);  // global float4 index in H
    const int slice = tid >> 6;              // 0..3

    const float4* base = (const float4*)(hs + (size_t)b * S_ * H_);

    float4 acc = make_float4(0.f, 0.f, 0.f, 0.f);
    float inv = 1.0f;

    if (seg == 0) {
        if (slice != 0) return;              // whole block is seg0: no sync below
        acc = base[h4];
    } else {
        const int* rng = (seg == 1 ? subj : obj) + b * 2;
        const int s0 = rng[0];
        const int s1 = rng[1];
        const int cnt = s1 - s0;
        inv = 1.0f / (float)(cnt > 0 ? cnt : 1);

        const int sb = s0 + slice;
        #pragma unroll
        for (int i = 0; i < 8; ++i) {        // 4 slices x 8 -> covers len 32
            const int s = sb + i * 4;
            if (s < s1) {
                const float4 v = base[(size_t)s * HC + h4];
                acc.x += v.x; acc.y += v.y; acc.z += v.z; acc.w += v.w;
            }
        }

        if (slice > 0) red[slice - 1][tid & 63] = acc;
        __syncthreads();
        if (slice != 0) return;
        const float4 r0 = red[0][tid & 63];
        const float4 r1 = red[1][tid & 63];
        const float4 r2 = red[2][tid & 63];
        acc.x += r0.x + r1.x + r2.x;
        acc.y += r0.y + r1.y + r2.y;
        acc.z += r0.z + r1.z + r2.z;
        acc.w += r0.w + r1.w + r2.w;
        acc.x *= inv; acc.y *= inv; acc.z *= inv; acc.w *= inv;
    }

    // split to bf16 hi/lo and store
    __nv_bfloat16 h[4], l[4];
    split_bf16(acc.x, h[0], l[0]);
    split_bf16(acc.y, h[1], l[1]);
    split_bf16(acc.z, h[2], l[2]);
    split_bf16(acc.w, h[3], l[3]);

    const size_t off = (size_t)b * K3 + seg * H_ + (size_t)h4 * 4;
    *(__nv_bfloat162*)(g_Ah + off)     = __halves2bfloat162(h[0], h[1]);
    *(__nv_bfloat162*)(g_Ah + off + 2) = __halves2bfloat162(h[2], h[3]);
    *(__nv_bfloat162*)(g_Al + off)     = __halves2bfloat162(l[0], l[1]);
    *(__nv_bfloat162*)(g_Al + off + 2) = __halves2bfloat162(l[2], l[3]);
}

// ---------------------------------------------------------------------------
// Kernel 2: split-bf16 3-term tensor-core GEMM partials.
// grid (16, 16) = 256 CTAs, 256 threads = 8 warps (2m x 4n).
// CTA tile 64m x 64n x 192k.  W [n][k] k-contiguous -> non-trans ldmatrix.
// ONE __syncthreads per stage: ldmatrix(cur) -> store(nxt) -> sync -> mma.
// f32->bf16 split happens at LOAD time (registers), off the sync path.
// ---------------------------------------------------------------------------
struct Stage { uint4 a; uint2 wh; uint2 wl; };

__global__ __launch_bounds__(256) void gemm_partial_kernel(
    const float* __restrict__ Wm)
{
    __shared__ __nv_bfloat16 sAh[2][B_ * ASTR];     // 3 KB x 2
    __shared__ __nv_bfloat16 sAl[2][B_ * ASTR];
    __shared__ __nv_bfloat16 sWh[2][BN_ * WSTR];    // 3 KB x 2
    __shared__ __nv_bfloat16 sWl[2][BN_ * WSTR];

    const int nb   = blockIdx.x;
    const int kb   = blockIdx.y;
    const int tid  = threadIdx.x;
    const int wid  = tid >> 5;
    const int lane = tid & 31;

    const int n0 = nb * BN_;
    const int k0 = kb * KC;

    // A: threads 0-127 load Ah, 128-255 load Al. One uint4 = 8 bf16.
    const int ar = (tid & 127) >> 1;        // row 0..63
    const int ap = tid & 1;                 // k-half of 16
    const __nv_bfloat16* aQ =
        (tid < 128 ? g_Ah : g_Al) + (size_t)ar * K3 + k0 + ap * 8;

    // W: one float4 (4 k) per thread per stage
    const int wrow = tid >> 2;              // 0..63
    const int wk4  = tid & 3;
    const float* wQ = Wm + (size_t)(n0 + wrow) * K3 + k0 + wk4 * 4;

    auto ld_st = [&](int st) {
        Stage q;
        q.a = *(const uint4*)(aQ + st * 16);
        const float4 w = *(const float4*)(wQ + st * 16);
        __nv_bfloat16 h0,h1,h2,h3,l0,l1,l2,l3;
        split_bf16(w.x, h0, l0); split_bf16(w.y, h1, l1);
        split_bf16(w.z, h2, l2); split_bf16(w.w, h3, l3);
        __nv_bfloat162 p;
        p = __halves2bfloat162(h0, h1); q.wh.x = *(uint32_t*)&p;
        p = __halves2bfloat162(h2, h3); q.wh.y = *(uint32_t*)&p;
        p = __halves2bfloat162(l0, l1); q.wl.x = *(uint32_t*)&p;
        p = __halves2bfloat162(l2, l3); q.wl.y = *(uint32_t*)&p;
        return q;
    };
    auto store_stage = [&](int buf, const Stage& q) {
        *(uint4*)((tid < 128 ? sAh[buf] : sAl[buf]) + ar * ASTR + ap * 8) = q.a;
        *(uint2*)(sWh[buf] + wrow * WSTR + wk4 * 4) = q.wh;
        *(uint2*)(sWl[buf] + wrow * WSTR + wk4 * 4) = q.wl;
    };

    // warp compute layout: 2 m-warps x 4 n-warps; warp tile 32m x 16n
    const int mw = wid & 1;
    const int nw = wid >> 1;

    const int a_row = (lane & 15);
    const int a_col = (lane >> 4) << 3;
    const int b_row = (lane & 7) | ((lane >> 4) << 3);
    const int b_col = ((lane >> 3) & 1) << 3;

    float acc[2][2][4];
    #pragma unroll
    for (int i = 0; i < 2; ++i)
        #pragma unroll
        for (int j = 0; j < 2; ++j)
            #pragma unroll
            for (int c = 0; c < 4; ++c) acc[i][j][c] = 0.f;

    // prologue: stage 0 -> smem buf0; stages 1..3 into register ring
    Stage q[3];
    q[0] = ld_st(0);
    store_stage(0, q[0]);
    q[1] = ld_st(1);                        // slot(s) = s % 3
    q[2] = ld_st(2);
    q[0] = ld_st(3);
    __syncthreads();

    #pragma unroll
    for (int t = 0; t < NSTG; ++t) {
        const int cur = t & 1;

        uint32_t ah[2][4], al[2][4], wh[4], wl[4];
        #pragma unroll
        for (int mi = 0; mi < 2; ++mi) {
            const int row = mw * 32 + mi * 16 + a_row;
            ldmatrix_x4(ah[mi], smem_u32(sAh[cur] + row * ASTR + a_col));
            ldmatrix_x4(al[mi], smem_u32(sAl[cur] + row * ASTR + a_col));
        }
        {
            const int row = nw * 16 + b_row;
            ldmatrix_x4(wh, smem_u32(sWh[cur] + row * WSTR + b_col));
            ldmatrix_x4(wl, smem_u32(sWl[cur] + row * WSTR + b_col));
        }

        if (t + 1 < NSTG) {
            store_stage(cur ^ 1, q[(t + 1) % 3]);      // writes buf nxt
            if (t + 4 < NSTG) q[(t + 1) % 3] = ld_st(t + 4);
            __syncthreads();   // orders: reads(cur)@t < writes(cur)@t+1,
                               //         writes(nxt)@t < reads(nxt)@t+1
        }

        #pragma unroll
        for (int mi = 0; mi < 2; ++mi)
            #pragma unroll
            for (int j = 0; j < 2; ++j) {
                const int hf = j * 2;
                mma_bf16(acc[mi][j], ah[mi], wh[hf], wh[hf + 1]); // ah*wh
                mma_bf16(acc[mi][j], ah[mi], wl[hf], wl[hf + 1]); // ah*wl
                mma_bf16(acc[mi][j], al[mi], wh[hf], wh[hf + 1]); // al*wh
            }
    }

    // epilogue: f32 partials
    const int c_row = lane >> 2;
    const int c_col = (lane & 3) * 2;
    float* pbase = g_part + (size_t)kb * (B_ * H_);
    #pragma unroll
    for (int mi = 0; mi < 2; ++mi) {
        #pragma unroll
        for (int j = 0; j < 2; ++j) {
            const int m = mw * 32 + mi * 16 + c_row;
            const int n = n0 + nw * 16 + j * 8 + c_col;
            *(float2*)(pbase + (size_t)m * H_ + n) =
                make_float2(acc[mi][j][0], acc[mi][j][1]);
            *(float2*)(pbase + (size_t)(m + 8) * H_ + n) =
                make_float2(acc[mi][j][2], acc[mi][j][3]);
        }
    }
}

// ---------------------------------------------------------------------------
// Kernel 3: reduce K-split partials + bias + tanh (float4 vectorized)
// grid 128 x 128 threads; each thread one float4 (4 outputs), 16 MLP loads
// ---------------------------------------------------------------------------
__global__ __launch_bounds__(128) void reduce_kernel(
    const float* __restrict__ bias,
    float* __restrict__ out)
{
    const int idx4 = blockIdx.x * 128 + threadIdx.x;  // 0 .. B_*H_/4-1
    const int n4 = idx4 & (H_ / 4 - 1);

    const float4 bv = *(const float4*)(bias + n4 * 4);
    float4 s = bv;
    #pragma unroll
    for (int kb = 0; kb < KS; ++kb) {
        const float4 p = *(const float4*)(g_part + (size_t)kb * (B_ * H_) + idx4 * 4);
        s.x += p.x; s.y += p.y; s.z += p.z; s.w += p.w;
    }

    float4 o;
    o.x = tanhf(s.x); o.y = tanhf(s.y); o.z = tanhf(s.z); o.w = tanhf(s.w);
    *(float4*)(out + idx4 * 4) = o;
}

// ---------------------------------------------------------------------------
extern "C" void kernel_launch(void* const* d_in, const int* in_sizes, int n_in,
                              void* d_out, int out_size)
{
    const float* hs   = (const float*)d_in[0];   // (B, S, H) f32
    const int*   subj = (const int*)  d_in[1];   // (B, 2) i32
    const int*   obj  = (const int*)  d_in[2];   // (B, 2) i32
    const float* Wm   = (const float*)d_in[3];   // (H, 3H) f32
    const float* bias = (const float*)d_in[4];   // (H,) f32
    float*       out  = (float*)d_out;           // (B, H) f32

    (void)in_sizes; (void)n_in; (void)out_size;

    feats_kernel<<<dim3(B_, 3, 4), 256>>>(hs, subj, obj);
    gemm_partial_kernel<<<dim3(H_ / BN_, KS), 256>>>(Wm);
    reduce_kernel<<<(B_ * H_) / 512, 128>>>(bias, out);
}